// round 11
// baseline (speedup 1.0000x reference)
#include <cuda_runtime.h>

// ---------------- problem constants ----------------
#define NUM_VARS 512
#define VAR_DIM  256
#define DIM      1024
#define NTOK     32768          // 8 * 4096
#define TOK_PER_CTA 32
#define NBLK     (NTOK / TOK_PER_CTA)   // 1024
#define KC       16
#define THREADS  256
#define EPSV     1e-7f

// d_out layout: [out | soft_probs | prob_perplexity | gumbel_probs(hard_x)]
#define OUT_OFF   0ULL
#define SOFT_OFF  8388608ULL               // 8*4096*256
#define PPL_OFF   25165824ULL              // + 32768*512
#define HARD_OFF  25165825ULL              // + 1

// ---------------- scratch (no allocations allowed) ----------------
__device__ float g_avg_partial[(size_t)NUM_VARS * NBLK];  // [var][blk]
__device__ float g_mask_partial[NBLK];

// ---------------- packed f32x2 helpers (Blackwell) ----------------
__device__ __forceinline__ void fma2(unsigned long long &acc,
                                     unsigned long long a,
                                     unsigned long long b) {
    asm("fma.rn.f32x2 %0, %1, %2, %0;" : "+l"(acc) : "l"(a), "l"(b));
}
__device__ __forceinline__ unsigned long long dup2(float w) {
    unsigned long long d;
    asm("mov.b64 %0, {%1, %1};" : "=l"(d) : "f"(w));
    return d;
}
__device__ __forceinline__ void unpack2(unsigned long long a, float &lo, float &hi) {
    asm("mov.b64 {%0, %1}, %2;" : "=f"(lo), "=f"(hi) : "l"(a));
}

// =====================================================================
// Fused kernel: GEMM (f32x2) + zero-col0 + mask + argmax + softmax +
//               one-hot + codebook gather + avg-prob partials
// =====================================================================
__global__ __launch_bounds__(THREADS, 2)
void typer_main(const float* __restrict__ x, const float* __restrict__ mask,
                const float* __restrict__ W, const float* __restrict__ cb,
                float* __restrict__ dout)
{
    __shared__ float sW[KC][NUM_VARS];       // 32 KB, [k][var]
    __shared__ float sX[KC][TOK_PER_CTA];    // 2 KB,  [k][tok]  (token pairs contiguous)
    __shared__ float sRedV[2][4];
    __shared__ int   sRedI[2][4];
    __shared__ float sRedS[2][4];
    __shared__ float sPart[2][NUM_VARS];     // 4 KB
    __shared__ float sMsk[2];

    const int tid  = threadIdx.x;
    const int v    = tid & 127;      // var lane 0..127  (owns vars v, v+128, v+256, v+384)
    const int r    = tid >> 7;       // token group 0..1 (owns tokens 16r .. 16r+15)
    const int lane = tid & 31;
    const int wg   = (tid >> 5) & 3; // warp within token group
    const int tok0 = blockIdx.x * TOK_PER_CTA;

    // acc[j][tp] : f32x2 = logits for tokens {16r+2tp, 16r+2tp+1}, var v+128j
    unsigned long long acc[4][8];
    #pragma unroll
    for (int j = 0; j < 4; ++j)
        #pragma unroll
        for (int tp = 0; tp < 8; ++tp) acc[j][tp] = 0ULL;

    // ---------------- GEMM main loop ----------------
    #pragma unroll 1
    for (int kc = 0; kc < DIM; kc += KC) {
        // W chunk, transposed to [k][var].  Coalesced 64B-per-4-lanes gmem reads.
        #pragma unroll
        for (int it = 0; it < 8; ++it) {
            int task = it * THREADS + tid;         // 0..2047
            int var  = task >> 2;
            int q    = task & 3;
            float4 w4 = *reinterpret_cast<const float4*>(
                            W + (size_t)var * DIM + kc + 4 * q);
            sW[4*q + 0][var] = w4.x;
            sW[4*q + 1][var] = w4.y;
            sW[4*q + 2][var] = w4.z;
            sW[4*q + 3][var] = w4.w;
        }
        // x chunk, transposed to [k][tok]
        if (tid < 128) {
            int t = tid >> 2;
            int q = tid & 3;
            float4 x4 = *reinterpret_cast<const float4*>(
                            x + (size_t)(tok0 + t) * DIM + kc + 4 * q);
            sX[4*q + 0][t] = x4.x;
            sX[4*q + 1][t] = x4.y;
            sX[4*q + 2][t] = x4.z;
            sX[4*q + 3][t] = x4.w;
        }
        __syncthreads();

        #pragma unroll
        for (int k = 0; k < KC; ++k) {
            unsigned long long xp[8];
            #pragma unroll
            for (int tp = 0; tp < 8; ++tp)   // LDS.64, warp-uniform (broadcast)
                xp[tp] = *reinterpret_cast<const unsigned long long*>(
                             &sX[k][16 * r + 2 * tp]);
            #pragma unroll
            for (int j = 0; j < 4; ++j) {
                unsigned long long wd = dup2(sW[k][v + 128 * j]); // coalesced LDS.32
                #pragma unroll
                for (int tp = 0; tp < 8; ++tp)
                    fma2(acc[j][tp], xp[tp], wd);                 // 32 FFMA2 / k / thread
            }
        }
        __syncthreads();
    }

    // ---------------- fused epilogue ----------------
    float avgacc[4] = {0.f, 0.f, 0.f, 0.f};
    float msum = 0.f;
    float* soft = dout + SOFT_OFF;
    float* hard = dout + HARD_OFF;
    float* outp = dout + OUT_OFF;

    #pragma unroll 1
    for (int i = 0; i < 16; ++i) {           // both token groups in lockstep
        int t    = 16 * r + i;
        int gtok = tok0 + t;
        float m  = mask[gtok];
        if (v == 0) msum += m;

        // extract logits, zero col 0, apply mask
        float l[4];
        int tp = i >> 1;
        #pragma unroll
        for (int j = 0; j < 4; ++j) {
            float lo, hi; unpack2(acc[j][tp], lo, hi);
            float val = (i & 1) ? hi : lo;
            if (v + 128 * j == 0) val = 0.f;
            l[j] = val * m;
        }

        // local argmax (ascending var order -> strict > keeps first index)
        float bv = l[0]; int bi = v;
        #pragma unroll
        for (int j = 1; j < 4; ++j)
            if (l[j] > bv) { bv = l[j]; bi = v + 128 * j; }
        // warp butterfly argmax, first-index tie-break
        #pragma unroll
        for (int off = 16; off; off >>= 1) {
            float ov = __shfl_xor_sync(0xffffffffu, bv, off);
            int   oi = __shfl_xor_sync(0xffffffffu, bi, off);
            if (ov > bv || (ov == bv && oi < bi)) { bv = ov; bi = oi; }
        }
        if (lane == 0) { sRedV[r][wg] = bv; sRedI[r][wg] = bi; }
        __syncthreads();
        float tmax = sRedV[r][0]; int targ = sRedI[r][0];
        #pragma unroll
        for (int w2 = 1; w2 < 4; ++w2) {
            float ov = sRedV[r][w2]; int oi = sRedI[r][w2];
            if (ov > tmax || (ov == tmax && oi < targ)) { tmax = ov; targ = oi; }
        }

        // softmax
        float e[4]; float s = 0.f;
        #pragma unroll
        for (int j = 0; j < 4; ++j) { e[j] = expf(l[j] - tmax); s += e[j]; }
        #pragma unroll
        for (int off = 16; off; off >>= 1)
            s += __shfl_xor_sync(0xffffffffu, s, off);
        if (lane == 0) sRedS[r][wg] = s;
        __syncthreads();
        float denom = sRedS[r][0] + sRedS[r][1] + sRedS[r][2] + sRedS[r][3];

        size_t rowbase = (size_t)gtok * NUM_VARS;
        #pragma unroll
        for (int j = 0; j < 4; ++j) {
            float p = e[j] / denom;
            soft[rowbase + v + 128 * j] = p;
            hard[rowbase + v + 128 * j] = (v + 128 * j == targ) ? 1.f : 0.f;
            avgacc[j] += p * m;
        }

        // out = codebook[targ] (row 0 of codebook is zeroed)
        float2 c;
        if (targ == 0) { c.x = 0.f; c.y = 0.f; }
        else c = *reinterpret_cast<const float2*>(cb + (size_t)targ * VAR_DIM + 2 * v);
        *reinterpret_cast<float2*>(outp + (size_t)gtok * VAR_DIM + 2 * v) = c;
    }

    // per-CTA partials (no atomics)
    #pragma unroll
    for (int j = 0; j < 4; ++j) sPart[r][v + 128 * j] = avgacc[j];
    if (v == 0) sMsk[r] = msum;
    __syncthreads();
    #pragma unroll
    for (int j = 0; j < 2; ++j) {
        int var = tid + 256 * j;
        g_avg_partial[(size_t)var * NBLK + blockIdx.x] =
            sPart[0][var] + sPart[1][var];
    }
    if (tid == 0) g_mask_partial[blockIdx.x] = sMsk[0] + sMsk[1];
}

// =====================================================================
// Finalize: avg_probs reduction + perplexity scalar
// =====================================================================
__global__ void typer_finalize(float* __restrict__ dout)
{
    __shared__ float sred[NUM_VARS];
    int tid = threadIdx.x;                // 512 threads, one per var

    // total mask
    float mloc = g_mask_partial[tid] + g_mask_partial[tid + 512];
    sred[tid] = mloc;
    __syncthreads();
    for (int off = 256; off; off >>= 1) {
        if (tid < off) sred[tid] += sred[tid + off];
        __syncthreads();
    }
    float mtot = sred[0];
    __syncthreads();

    // avg_probs[tid]
    float a = 0.f;
    const float* p = g_avg_partial + (size_t)tid * NBLK;
    #pragma unroll 4
    for (int c = 0; c < NBLK; c += 4) {
        float4 v4 = *reinterpret_cast<const float4*>(p + c);
        a += v4.x + v4.y + v4.z + v4.w;
    }
    a /= mtot;

    float term = a * logf(a + EPSV);
    sred[tid] = term;
    __syncthreads();
    for (int off = 256; off; off >>= 1) {
        if (tid < off) sred[tid] += sred[tid + off];
        __syncthreads();
    }
    if (tid == 0) dout[PPL_OFF] = expf(-sred[0]);
}

// =====================================================================
extern "C" void kernel_launch(void* const* d_in, const int* in_sizes, int n_in,
                              void* d_out, int out_size)
{
    const float* x    = (const float*)d_in[0];   // [8,4096,1024]
    const float* mask = (const float*)d_in[1];   // [8,4096]
    const float* W    = (const float*)d_in[2];   // [512,1024]
    const float* cb   = (const float*)d_in[3];   // [512,256]
    float* out = (float*)d_out;

    typer_main<<<NBLK, THREADS>>>(x, mask, W, cb, out);
    typer_finalize<<<1, NUM_VARS>>>(out);
}